// round 8
// baseline (speedup 1.0000x reference)
#include <cuda_runtime.h>
#include <cuda_bf16.h>
#include <cstdint>

// SocialPooling: prep kernel (H->bf16 hi/lo + neighbor bitmasks + W fragments)
// then a tensor-core GEMM kernel processing active cells in PAIRS:
// one H-fragment LDSM pair feeds 8 MMAs (2 cells x 2 tiles) -> half the LDSM
// traffic of R7 and denser MMA issue.

#define TPB 128

// ---- gemm smem layout ----
#define SM_HHI   0        // 16 KB (reused as fp32 staging for combine)
#define SM_HLO   16384    // 16 KB
#define SM_BM    32768    // u64 [16 cell][32 row] = 4 KB
#define SM_FLAG  36864    // u32[16]
#define SM_LIST  36928    // u8[16] + u32 count
#define SMEM_GEMM 36992

// ---- prep smem ----
#define PM_PX    0
#define PM_PY    256
#define PM_PM    512      // u64 [16 cell][64 row][2 half] = 16 KB
#define SMEM_PREP 16896

__device__ char g_hbuf[256 * 32768];                 // per scene: 16KB hi + 16KB lo
__device__ unsigned long long g_bm[256 * 16 * 64];   // [scene][cell][row]
__device__ uint4 g_wfrags[16 * 8 * 8 * 32];          // [g][k16][n8][lane]

__device__ __forceinline__ uint32_t smem_u32(const void* p) {
    uint32_t a;
    asm("{ .reg .u64 t; cvta.to.shared.u64 t, %1; cvt.u32.u64 %0, t; }" : "=r"(a) : "l"(p));
    return a;
}
__device__ __forceinline__ uint32_t pack_bf16x2(float lo, float hi) {
    uint32_t r;
    asm("cvt.rn.satfinite.bf16x2.f32 %0, %1, %2;" : "=r"(r) : "f"(hi), "f"(lo));
    return r;
}
__device__ __forceinline__ float bflo(uint32_t p) { return __uint_as_float(p << 16); }
__device__ __forceinline__ float bfhi(uint32_t p) { return __uint_as_float(p & 0xFFFF0000u); }

__device__ __forceinline__ uint32_t mbits(unsigned long long v) {
    uint32_t r = (v & 1ull) ? 0x3F80u : 0u;
    if (v & 2ull) r |= 0x3F800000u;
    return r;
}

#define LDMX4T(r0, r1, r2, r3, addr) \
    asm volatile("ldmatrix.sync.aligned.m8n8.x4.trans.shared.b16 {%0,%1,%2,%3}, [%4];" \
                 : "=r"(r0), "=r"(r1), "=r"(r2), "=r"(r3) : "r"(addr))

#define MMA_BF16(d, a0, a1, a2, a3, b0, b1) \
    asm volatile("mma.sync.aligned.m16n8k16.row.col.f32.bf16.bf16.f32 " \
                 "{%0,%1,%2,%3}, {%4,%5,%6,%7}, {%8,%9}, {%0,%1,%2,%3};" \
                 : "+f"((d)[0]), "+f"((d)[1]), "+f"((d)[2]), "+f"((d)[3]) \
                 : "r"(a0), "r"(a1), "r"(a2), "r"(a3), "r"(b0), "r"(b1))

// ---------------- prep: H convert + bitmasks (bx<256), W fragments (bx>=256) ----------------
__global__ __launch_bounds__(TPB, 4)
void sp_prep(const float* __restrict__ hidden,
             const float* __restrict__ pos,
             const float* __restrict__ weight)
{
    const int tid = threadIdx.x;

    if (blockIdx.x >= 256) {
        int idx  = (blockIdx.x - 256) * TPB + tid;   // 0..32767
        int lane = idx & 31;
        int n8   = (idx >> 5) & 7;
        int k16  = (idx >> 8) & 7;
        int g    = idx >> 11;
        int n  = n8 * 8 + (lane >> 2);
        int k0 = g * 128 + k16 * 16 + (lane & 3) * 2;
        float w00 = weight[(size_t)(k0 + 0) * 64 + n];
        float w01 = weight[(size_t)(k0 + 1) * 64 + n];
        float w10 = weight[(size_t)(k0 + 8) * 64 + n];
        float w11 = weight[(size_t)(k0 + 9) * 64 + n];
        uint32_t h0 = pack_bf16x2(w00, w01);
        uint32_t h1 = pack_bf16x2(w10, w11);
        uint32_t l0 = pack_bf16x2(w00 - bflo(h0), w01 - bfhi(h0));
        uint32_t l1 = pack_bf16x2(w10 - bflo(h1), w11 - bfhi(h1));
        g_wfrags[idx] = make_uint4(h0, h1, l0, l1);
        return;
    }

    extern __shared__ char smem[];
    const int b = blockIdx.x;
    float* px = (float*)(smem + PM_PX);
    float* py = (float*)(smem + PM_PY);
    unsigned long long* pm = (unsigned long long*)(smem + PM_PM);

    if (tid < 64) {
        px[tid] = pos[((size_t)b * 64 + tid) * 2 + 0];
        py[tid] = pos[((size_t)b * 64 + tid) * 2 + 1];
    }
    #pragma unroll
    for (int it = 0; it < 16; it++) pm[tid + it * TPB] = 0ull;

    char* hb = g_hbuf + (size_t)b * 32768;
    #pragma unroll
    for (int it = 0; it < 8; it++) {
        int cid = tid + it * TPB;
        int row = cid >> 4;
        int ch  = cid & 15;
        const float4* src = (const float4*)(hidden + ((size_t)b * 64 + row) * 128 + ch * 8);
        float4 v0 = src[0], v1 = src[1];
        uint32_t h0 = pack_bf16x2(v0.x, v0.y);
        uint32_t h1 = pack_bf16x2(v0.z, v0.w);
        uint32_t h2 = pack_bf16x2(v1.x, v1.y);
        uint32_t h3 = pack_bf16x2(v1.z, v1.w);
        uint32_t l0 = pack_bf16x2(v0.x - bflo(h0), v0.y - bfhi(h0));
        uint32_t l1 = pack_bf16x2(v0.z - bflo(h1), v0.w - bfhi(h1));
        uint32_t l2 = pack_bf16x2(v1.x - bflo(h2), v1.y - bfhi(h2));
        uint32_t l3 = pack_bf16x2(v1.z - bflo(h3), v1.w - bfhi(h3));
        uint32_t off = (uint32_t)(row * 256 + ((ch ^ (row & 7)) << 4));
        *(uint4*)(hb + off)         = make_uint4(h0, h1, h2, h3);
        *(uint4*)(hb + 16384 + off) = make_uint4(l0, l1, l2, l3);
    }
    __syncthreads();

    {
        const int i    = tid >> 1;
        const int half = tid & 1;
        const float xi = px[i], yi = py[i];
        const int j0 = half * 32;
        for (int jj = 0; jj < 32; jj++) {
            int j = j0 + jj;
            float dx = px[j] - xi, dy = py[j] - yi;
            if (j != i && fabsf(dx) <= 2.0f && fabsf(dy) <= 2.0f) {
                int gx = min(3, max(0, (int)floorf(dx + 2.0f)));
                int gy = min(3, max(0, (int)floorf(dy + 2.0f)));
                pm[((gy * 4 + gx) * 64 + i) * 2 + half] |= (1ull << j);
            }
        }
    }
    __syncthreads();

    unsigned long long* dst = g_bm + (size_t)b * 1024;
    #pragma unroll
    for (int it = 0; it < 8; it++) {
        int w = tid + it * TPB;
        dst[w] = pm[w * 2] | pm[w * 2 + 1];
    }
}

// ---------------- gemm: CTA = 32 rows, cells processed in pairs ----------------
__global__ __launch_bounds__(TPB, 4)
void sp_gemm(const float* __restrict__ bias, float* __restrict__ out)
{
    extern __shared__ char smem[];
    const int tid  = threadIdx.x;
    const int lane = tid & 31;
    const int wid  = tid >> 5;
    const int b    = blockIdx.x >> 1;
    const int r0   = (blockIdx.x & 1) * 32;

    unsigned long long* sbm = (unsigned long long*)(smem + SM_BM);
    uint32_t* flag = (uint32_t*)(smem + SM_FLAG);
    unsigned char* clist = (unsigned char*)(smem + SM_LIST);
    int* nact = (int*)(smem + SM_LIST + 16);

    // H copy (already bf16 hi/lo in final byte layout)
    {
        const uint4* src = (const uint4*)(g_hbuf + (size_t)b * 32768);
        uint4* dst = (uint4*)smem;
        #pragma unroll
        for (int it = 0; it < 16; it++) dst[tid + it * TPB] = src[tid + it * TPB];
    }
    // mask copy: our 32 rows of each cell
    {
        const unsigned long long* src = g_bm + (size_t)b * 1024 + r0;
        #pragma unroll
        for (int it = 0; it < 4; it++) {
            int idx = tid + it * TPB;
            int c = idx >> 5, r = idx & 31;
            sbm[idx] = src[c * 64 + r];
        }
    }
    __syncthreads();
    if (tid < 16) {
        unsigned long long o = 0;
        #pragma unroll 8
        for (int i = 0; i < 32; i++) o |= sbm[tid * 32 + i];
        flag[tid] = (o != 0ull) ? 1u : 0u;
    }
    __syncthreads();
    if (tid == 0) {
        int n = 0;
        #pragma unroll
        for (int c = 0; c < 16; c++) if (flag[c]) clist[n++] = (unsigned char)c;
        *nact = n;
    }
    __syncthreads();

    const int strip = wid >> 1;
    const int khalf = wid & 1;
    const int il0   = strip * 16;
    const int qr = lane >> 2;
    const int qc = (lane & 3) * 2;

    float oacc[8][4];
    #pragma unroll
    for (int nb = 0; nb < 8; nb++) {
        oacc[nb][0] = 0.f; oacc[nb][1] = 0.f; oacc[nb][2] = 0.f; oacc[nb][3] = 0.f;
    }

    const uint32_t sbu = smem_u32(smem);
    const uint32_t hrow_off = (uint32_t)((((lane >> 3) & 1) * 8 + (lane & 7)) * 256);
    const uint32_t cb = (uint32_t)(lane >> 4);
    const uint32_t l7 = (uint32_t)(lane & 7);

    const int na = *nact;
    for (int p = 0; p < na; p += 2) {
        const int g0 = clist[p];
        const bool has1 = (p + 1) < na;
        const int g1 = has1 ? clist[p + 1] : 0;

        const unsigned long long m00 = sbm[g0 * 32 + il0 + qr];
        const unsigned long long m01 = sbm[g0 * 32 + il0 + 8 + qr];
        const unsigned long long m10 = has1 ? sbm[g1 * 32 + il0 + qr] : 0ull;
        const unsigned long long m11 = has1 ? sbm[g1 * 32 + il0 + 8 + qr] : 0ull;

        // A-fragments for both cells, all 4 t-steps (hoisted: no redundancy)
        uint32_t A0[4][4], A1[4][4];
        #pragma unroll
        for (int t = 0; t < 4; t++) {
            const int sh = t * 16 + qc;
            A0[t][0] = mbits(m00 >> sh);
            A0[t][1] = mbits(m01 >> sh);
            A0[t][2] = mbits(m00 >> (sh + 8));
            A0[t][3] = mbits(m01 >> (sh + 8));
            A1[t][0] = mbits(m10 >> sh);
            A1[t][1] = mbits(m11 >> sh);
            A1[t][2] = mbits(m10 >> (sh + 8));
            A1[t][3] = mbits(m11 >> (sh + 8));
        }

        #pragma unroll
        for (int hc = 0; hc < 4; hc++) {
            // ---- stage 1 for this h-chunk: one LDSM pair feeds 8 MMAs ----
            float s0a[4] = {0.f, 0.f, 0.f, 0.f};
            float s0b[4] = {0.f, 0.f, 0.f, 0.f};
            float s1a[4] = {0.f, 0.f, 0.f, 0.f};
            float s1b[4] = {0.f, 0.f, 0.f, 0.f};
            const uint32_t ch = (uint32_t)(khalf * 8 + hc * 2) + cb;
            const uint32_t choff = ((ch ^ l7) << 4);
            #pragma unroll
            for (int t = 0; t < 4; t++) {
                const uint32_t off = hrow_off + (uint32_t)t * 4096 + choff;
                uint32_t bh0, bh1, bh2, bh3, bl0, bl1, bl2, bl3;
                LDMX4T(bh0, bh1, bh2, bh3, sbu + SM_HHI + off);
                LDMX4T(bl0, bl1, bl2, bl3, sbu + SM_HLO + off);
                MMA_BF16(s0a, A0[t][0], A0[t][1], A0[t][2], A0[t][3], bh0, bh1);
                MMA_BF16(s0b, A0[t][0], A0[t][1], A0[t][2], A0[t][3], bh2, bh3);
                MMA_BF16(s1a, A1[t][0], A1[t][1], A1[t][2], A1[t][3], bh0, bh1);
                MMA_BF16(s1b, A1[t][0], A1[t][1], A1[t][2], A1[t][3], bh2, bh3);
                MMA_BF16(s0a, A0[t][0], A0[t][1], A0[t][2], A0[t][3], bl0, bl1);
                MMA_BF16(s0b, A0[t][0], A0[t][1], A0[t][2], A0[t][3], bl2, bl3);
                MMA_BF16(s1a, A1[t][0], A1[t][1], A1[t][2], A1[t][3], bl0, bl1);
                MMA_BF16(s1b, A1[t][0], A1[t][1], A1[t][2], A1[t][3], bl2, bl3);
            }

            // ---- stage 2 for both cells, k16 chunk kk = khalf*4 + hc ----
            const int kk = khalf * 4 + hc;
            #pragma unroll
            for (int c = 0; c < 2; c++) {
                if (c == 1 && !has1) break;
                const float* s0 = (c == 0) ? s0a : s1a;
                const float* s1 = (c == 0) ? s0b : s1b;
                const int gg = (c == 0) ? g0 : g1;
                uint32_t ah0 = pack_bf16x2(s0[0], s0[1]);
                uint32_t ah1 = pack_bf16x2(s0[2], s0[3]);
                uint32_t ah2 = pack_bf16x2(s1[0], s1[1]);
                uint32_t ah3 = pack_bf16x2(s1[2], s1[3]);
                uint32_t al0 = pack_bf16x2(s0[0] - bflo(ah0), s0[1] - bfhi(ah0));
                uint32_t al1 = pack_bf16x2(s0[2] - bflo(ah1), s0[3] - bfhi(ah1));
                uint32_t al2 = pack_bf16x2(s1[0] - bflo(ah2), s1[1] - bfhi(ah2));
                uint32_t al3 = pack_bf16x2(s1[2] - bflo(ah3), s1[3] - bfhi(ah3));
                const uint4* wp = g_wfrags + (size_t)((gg * 8 + kk) * 8) * 32 + lane;
                #pragma unroll
                for (int nbh = 0; nbh < 2; nbh++) {
                    uint4 w0 = wp[(nbh * 4 + 0) * 32];
                    uint4 w1 = wp[(nbh * 4 + 1) * 32];
                    uint4 w2 = wp[(nbh * 4 + 2) * 32];
                    uint4 w3 = wp[(nbh * 4 + 3) * 32];
                    float* o0 = oacc[nbh * 4 + 0];
                    float* o1 = oacc[nbh * 4 + 1];
                    float* o2 = oacc[nbh * 4 + 2];
                    float* o3 = oacc[nbh * 4 + 3];
                    MMA_BF16(o0, ah0, ah1, ah2, ah3, w0.x, w0.y);
                    MMA_BF16(o1, ah0, ah1, ah2, ah3, w1.x, w1.y);
                    MMA_BF16(o2, ah0, ah1, ah2, ah3, w2.x, w2.y);
                    MMA_BF16(o3, ah0, ah1, ah2, ah3, w3.x, w3.y);
                    MMA_BF16(o0, ah0, ah1, ah2, ah3, w0.z, w0.w);
                    MMA_BF16(o1, ah0, ah1, ah2, ah3, w1.z, w1.w);
                    MMA_BF16(o2, ah0, ah1, ah2, ah3, w2.z, w2.w);
                    MMA_BF16(o3, ah0, ah1, ah2, ah3, w3.z, w3.w);
                    MMA_BF16(o0, al0, al1, al2, al3, w0.x, w0.y);
                    MMA_BF16(o1, al0, al1, al2, al3, w1.x, w1.y);
                    MMA_BF16(o2, al0, al1, al2, al3, w2.x, w2.y);
                    MMA_BF16(o3, al0, al1, al2, al3, w3.x, w3.y);
                }
            }
        }
    }

    // ---- combine k-halves via smem (reuse H region as fp32 staging) ----
    __syncthreads();
    float* stg = (float*)(smem + SM_HHI);   // [4 warps][16 rows][64 n]
    {
        float* wbase = stg + wid * 1024;
        #pragma unroll
        for (int nb = 0; nb < 8; nb++) {
            *(float2*)(wbase + qr * 64 + nb * 8 + qc)       = make_float2(oacc[nb][0], oacc[nb][1]);
            *(float2*)(wbase + (qr + 8) * 64 + nb * 8 + qc) = make_float2(oacc[nb][2], oacc[nb][3]);
        }
    }
    __syncthreads();

    {
        float* orow = out + ((size_t)b * 64 + r0) * 64;
        #pragma unroll
        for (int q = 0; q < 4; q++) {
            int e  = tid * 16 + q * 4;
            int rl = e >> 6;
            int n  = e & 63;
            int s  = rl >> 4;
            int rr = rl & 15;
            float4 a = *(float4*)(stg + (2 * s) * 1024 + rr * 64 + n);
            float4 c = *(float4*)(stg + (2 * s + 1) * 1024 + rr * 64 + n);
            float4 bv = *(const float4*)(bias + n);
            *(float4*)(orow + rl * 64 + n) =
                make_float4(a.x + c.x + bv.x, a.y + c.y + bv.y,
                            a.z + c.z + bv.z, a.w + c.w + bv.w);
        }
    }
}

extern "C" void kernel_launch(void* const* d_in, const int* in_sizes, int n_in,
                              void* d_out, int out_size)
{
    const float* hidden = (const float*)d_in[0];
    const float* pos    = (const float*)d_in[1];
    const float* weight = (const float*)d_in[2];
    const float* bias   = (const float*)d_in[3];
    float* out = (float*)d_out;

    const int total = in_sizes[0] / 128;     // 16384 rows
    const int nscene = total / 64;           // 256

    cudaFuncSetAttribute(sp_prep, cudaFuncAttributeMaxDynamicSharedMemorySize, SMEM_PREP);
    sp_prep<<<nscene + 256, TPB, SMEM_PREP>>>(hidden, pos, weight);

    cudaFuncSetAttribute(sp_gemm, cudaFuncAttributeMaxDynamicSharedMemorySize, SMEM_GEMM);
    sp_gemm<<<nscene * 2, TPB, SMEM_GEMM>>>(bias, out);
}

// round 9
// speedup vs baseline: 1.1493x; 1.1493x over previous
#include <cuda_runtime.h>
#include <cuda_bf16.h>
#include <cstdint>

// SocialPooling: monolithic tensor-core kernel (R7 core, single launch wave).
//   stage1: S_g[16 rows x h-half] = M_g[rows x 64(0/1)] @ (H_hi+H_lo)
//   stage2: out_partial += S_hi@W_hi + S_hi@W_lo + S_lo@W_hi
// CTA = 1 scene (64 rows), TPB=256: 8 warps = 4 row-strips x 2 k-halves.
// In-kernel prep (H->bf16 hi/lo once per scene + bitmasks); W frags via tiny
// prep kernel. launch_bounds(256,2): 2 CTAs/SM, grid 256 = one wave.

#define TPB 256

// ---- smem layout ----
#define SM_HHI   0        // bf16 [64 row][128 h] swizzled = 16 KB (reused for staging)
#define SM_HLO   16384    // 16 KB (reused for staging)
#define SM_BM    32768    // u64 [16 cell][64 row] = 8 KB
#define SM_FLAG  40960    // u32[16]
#define SM_PX    41024    // float[64]
#define SM_PY    41280    // float[64]
#define SMEM_MAIN 41536

__device__ uint4 g_wfrags[16 * 8 * 8 * 32];          // [g][k16][n8][lane]

__device__ __forceinline__ uint32_t smem_u32(const void* p) {
    uint32_t a;
    asm("{ .reg .u64 t; cvta.to.shared.u64 t, %1; cvt.u32.u64 %0, t; }" : "=r"(a) : "l"(p));
    return a;
}
__device__ __forceinline__ uint32_t pack_bf16x2(float lo, float hi) {
    uint32_t r;
    asm("cvt.rn.satfinite.bf16x2.f32 %0, %1, %2;" : "=r"(r) : "f"(hi), "f"(lo));
    return r;
}
__device__ __forceinline__ float bflo(uint32_t p) { return __uint_as_float(p << 16); }
__device__ __forceinline__ float bfhi(uint32_t p) { return __uint_as_float(p & 0xFFFF0000u); }

__device__ __forceinline__ uint32_t mbits(unsigned long long v) {
    uint32_t r = (v & 1ull) ? 0x3F80u : 0u;
    if (v & 2ull) r |= 0x3F800000u;
    return r;
}

#define LDMX4T(r0, r1, r2, r3, addr) \
    asm volatile("ldmatrix.sync.aligned.m8n8.x4.trans.shared.b16 {%0,%1,%2,%3}, [%4];" \
                 : "=r"(r0), "=r"(r1), "=r"(r2), "=r"(r3) : "r"(addr))

#define MMA_BF16(d, a0, a1, a2, a3, b0, b1) \
    asm volatile("mma.sync.aligned.m16n8k16.row.col.f32.bf16.bf16.f32 " \
                 "{%0,%1,%2,%3}, {%4,%5,%6,%7}, {%8,%9}, {%0,%1,%2,%3};" \
                 : "+f"((d)[0]), "+f"((d)[1]), "+f"((d)[2]), "+f"((d)[3]) \
                 : "r"(a0), "r"(a1), "r"(a2), "r"(a3), "r"(b0), "r"(b1))

// ---------------- W prep: fragment-order hi/lo split (tiny) ----------------
__global__ void sp_wprep(const float* __restrict__ weight) {
    int idx  = blockIdx.x * 256 + threadIdx.x;   // 0..32767
    int lane = idx & 31;
    int n8   = (idx >> 5) & 7;
    int k16  = (idx >> 8) & 7;
    int g    = idx >> 11;
    int n  = n8 * 8 + (lane >> 2);
    int k0 = g * 128 + k16 * 16 + (lane & 3) * 2;
    float w00 = weight[(size_t)(k0 + 0) * 64 + n];
    float w01 = weight[(size_t)(k0 + 1) * 64 + n];
    float w10 = weight[(size_t)(k0 + 8) * 64 + n];
    float w11 = weight[(size_t)(k0 + 9) * 64 + n];
    uint32_t h0 = pack_bf16x2(w00, w01);
    uint32_t h1 = pack_bf16x2(w10, w11);
    uint32_t l0 = pack_bf16x2(w00 - bflo(h0), w01 - bfhi(h0));
    uint32_t l1 = pack_bf16x2(w10 - bflo(h1), w11 - bfhi(h1));
    g_wfrags[idx] = make_uint4(h0, h1, l0, l1);
}

// ---------------- main: CTA = 1 scene, 8 warps = 4 strips x 2 k-halves ----------------
__global__ __launch_bounds__(TPB, 2)
void sp_main(const float* __restrict__ hidden,
             const float* __restrict__ pos,
             const float* __restrict__ bias,
             float* __restrict__ out)
{
    extern __shared__ char smem[];
    const int tid  = threadIdx.x;
    const int lane = tid & 31;
    const int wid  = tid >> 5;
    const int b    = blockIdx.x;

    unsigned long long* sbm = (unsigned long long*)(smem + SM_BM);
    uint32_t* flag = (uint32_t*)(smem + SM_FLAG);
    float* px = (float*)(smem + SM_PX);
    float* py = (float*)(smem + SM_PY);

    if (tid < 64) {
        px[tid] = pos[((size_t)b * 64 + tid) * 2 + 0];
        py[tid] = pos[((size_t)b * 64 + tid) * 2 + 1];
    }
    #pragma unroll
    for (int it = 0; it < 4; it++) sbm[tid + it * TPB] = 0ull;

    // H -> smem bf16 hi/lo (once per scene), rows of 256B, 16B-chunk swizzle
    #pragma unroll
    for (int it = 0; it < 4; it++) {
        int cid = tid + it * TPB;          // 0..1023 = row*16 + chunk
        int row = cid >> 4;
        int ch  = cid & 15;
        const float4* src = (const float4*)(hidden + ((size_t)b * 64 + row) * 128 + ch * 8);
        float4 v0 = src[0], v1 = src[1];
        uint32_t h0 = pack_bf16x2(v0.x, v0.y);
        uint32_t h1 = pack_bf16x2(v0.z, v0.w);
        uint32_t h2 = pack_bf16x2(v1.x, v1.y);
        uint32_t h3 = pack_bf16x2(v1.z, v1.w);
        uint32_t l0 = pack_bf16x2(v0.x - bflo(h0), v0.y - bfhi(h0));
        uint32_t l1 = pack_bf16x2(v0.z - bflo(h1), v0.w - bfhi(h1));
        uint32_t l2 = pack_bf16x2(v1.x - bflo(h2), v1.y - bfhi(h2));
        uint32_t l3 = pack_bf16x2(v1.z - bflo(h3), v1.w - bfhi(h3));
        uint32_t off = (uint32_t)(row * 256 + ((ch ^ (row & 7)) << 4));
        *(uint4*)(smem + SM_HHI + off) = make_uint4(h0, h1, h2, h3);
        *(uint4*)(smem + SM_HLO + off) = make_uint4(l0, l1, l2, l3);
    }
    __syncthreads();

    // neighbor bitmasks: 2 threads per row i (each scans 32 j), merged via atomicOr-free
    // halves: thread(half) ORs into its own 32-bit range of the same u64 -> no race
    if (tid < 128) {
        const int i    = tid >> 1;
        const int half = tid & 1;
        const float xi = px[i], yi = py[i];
        const int j0 = half * 32;
        unsigned long long acc[16];
        #pragma unroll
        for (int c = 0; c < 16; c++) acc[c] = 0ull;
        for (int jj = 0; jj < 32; jj++) {
            int j = j0 + jj;
            float dx = px[j] - xi, dy = py[j] - yi;
            if (j != i && fabsf(dx) <= 2.0f && fabsf(dy) <= 2.0f) {
                int gx = min(3, max(0, (int)floorf(dx + 2.0f)));
                int gy = min(3, max(0, (int)floorf(dy + 2.0f)));
                acc[gy * 4 + gx] |= (1ull << j);
            }
        }
        // halves write disjoint 32-bit words of sbm[c*64+i]
        #pragma unroll
        for (int c = 0; c < 16; c++) {
            unsigned int v = (unsigned int)(acc[c] >> (half * 32));
            if (v) ((unsigned int*)&sbm[c * 64 + i])[half] = v;
        }
    }
    __syncthreads();
    if (tid < 16) {
        unsigned long long o = 0;
        #pragma unroll 8
        for (int i = 0; i < 64; i++) o |= sbm[tid * 64 + i];
        flag[tid] = (o != 0ull) ? 1u : 0u;
    }
    __syncthreads();

    // ---- warp mapping: 4 strips x 2 k-halves ----
    const int strip = wid >> 1;            // 0..3
    const int khalf = wid & 1;
    const int il0   = strip * 16;
    const int qr = lane >> 2;
    const int qc = (lane & 3) * 2;

    float oacc[8][4];
    #pragma unroll
    for (int nb = 0; nb < 8; nb++) {
        oacc[nb][0] = 0.f; oacc[nb][1] = 0.f; oacc[nb][2] = 0.f; oacc[nb][3] = 0.f;
    }

    const uint32_t sbu = smem_u32(smem);
    const uint32_t hrow_off = (uint32_t)((((lane >> 3) & 1) * 8 + (lane & 7)) * 256);
    const uint32_t cb = (uint32_t)(lane >> 4);
    const uint32_t l7 = (uint32_t)(lane & 7);

    for (int g = 0; g < 16; g++) {
        if (flag[g] == 0u) continue;

        const unsigned long long m0 = sbm[g * 64 + il0 + qr];
        const unsigned long long m1 = sbm[g * 64 + il0 + 8 + qr];

        // ---- stage 1: S for our h-half, 8 independent accumulator chains ----
        float sacc[8][4];
        #pragma unroll
        for (int t = 0; t < 8; t++) {
            sacc[t][0] = 0.f; sacc[t][1] = 0.f; sacc[t][2] = 0.f; sacc[t][3] = 0.f;
        }
        #pragma unroll
        for (int t = 0; t < 4; t++) {
            const int sh = t * 16 + qc;
            const uint32_t a0 = mbits(m0 >> sh);
            const uint32_t a1 = mbits(m1 >> sh);
            const uint32_t a2 = mbits(m0 >> (sh + 8));
            const uint32_t a3 = mbits(m1 >> (sh + 8));
            const uint32_t rowoff = hrow_off + (uint32_t)t * 4096;
            #pragma unroll
            for (int hc = 0; hc < 4; hc++) {
                const uint32_t ch  = (uint32_t)(khalf * 8 + hc * 2) + cb;
                const uint32_t off = rowoff + ((ch ^ l7) << 4);
                uint32_t bh0, bh1, bh2, bh3, bl0, bl1, bl2, bl3;
                LDMX4T(bh0, bh1, bh2, bh3, sbu + SM_HHI + off);
                LDMX4T(bl0, bl1, bl2, bl3, sbu + SM_HLO + off);
                MMA_BF16(sacc[2 * hc],     a0, a1, a2, a3, bh0, bh1);
                MMA_BF16(sacc[2 * hc + 1], a0, a1, a2, a3, bh2, bh3);
                MMA_BF16(sacc[2 * hc],     a0, a1, a2, a3, bl0, bl1);
                MMA_BF16(sacc[2 * hc + 1], a0, a1, a2, a3, bl2, bl3);
            }
        }

        // ---- stage 2: our k16 chunks (khalf*4 + hc), nb in 2 groups of 4 ----
        #pragma unroll
        for (int hc = 0; hc < 4; hc++) {
            const float* s0 = sacc[2 * hc];
            const float* s1 = sacc[2 * hc + 1];
            uint32_t ah0 = pack_bf16x2(s0[0], s0[1]);
            uint32_t ah1 = pack_bf16x2(s0[2], s0[3]);
            uint32_t ah2 = pack_bf16x2(s1[0], s1[1]);
            uint32_t ah3 = pack_bf16x2(s1[2], s1[3]);
            uint32_t al0 = pack_bf16x2(s0[0] - bflo(ah0), s0[1] - bfhi(ah0));
            uint32_t al1 = pack_bf16x2(s0[2] - bflo(ah1), s0[3] - bfhi(ah1));
            uint32_t al2 = pack_bf16x2(s1[0] - bflo(ah2), s1[1] - bfhi(ah2));
            uint32_t al3 = pack_bf16x2(s1[2] - bflo(ah3), s1[3] - bfhi(ah3));
            const int kk = khalf * 4 + hc;
            const uint4* wp = g_wfrags + (size_t)((g * 8 + kk) * 8) * 32 + lane;
            #pragma unroll
            for (int nbh = 0; nbh < 2; nbh++) {
                uint4 w0 = wp[(nbh * 4 + 0) * 32];
                uint4 w1 = wp[(nbh * 4 + 1) * 32];
                uint4 w2 = wp[(nbh * 4 + 2) * 32];
                uint4 w3 = wp[(nbh * 4 + 3) * 32];
                float* o0 = oacc[nbh * 4 + 0];
                float* o1 = oacc[nbh * 4 + 1];
                float* o2 = oacc[nbh * 4 + 2];
                float* o3 = oacc[nbh * 4 + 3];
                MMA_BF16(o0, ah0, ah1, ah2, ah3, w0.x, w0.y);
                MMA_BF16(o1, ah0, ah1, ah2, ah3, w1.x, w1.y);
                MMA_BF16(o2, ah0, ah1, ah2, ah3, w2.x, w2.y);
                MMA_BF16(o3, ah0, ah1, ah2, ah3, w3.x, w3.y);
                MMA_BF16(o0, ah0, ah1, ah2, ah3, w0.z, w0.w);
                MMA_BF16(o1, ah0, ah1, ah2, ah3, w1.z, w1.w);
                MMA_BF16(o2, ah0, ah1, ah2, ah3, w2.z, w2.w);
                MMA_BF16(o3, ah0, ah1, ah2, ah3, w3.z, w3.w);
                MMA_BF16(o0, al0, al1, al2, al3, w0.x, w0.y);
                MMA_BF16(o1, al0, al1, al2, al3, w1.x, w1.y);
                MMA_BF16(o2, al0, al1, al2, al3, w2.x, w2.y);
                MMA_BF16(o3, al0, al1, al2, al3, w3.x, w3.y);
            }
        }
    }

    // ---- combine k-halves via smem (reuse H region as fp32 staging) ----
    __syncthreads();                        // all warps done reading H
    float* stg = (float*)(smem + SM_HHI);   // [8 warps][16 rows][64 n] = 32 KB
    {
        float* wbase = stg + wid * 1024;
        #pragma unroll
        for (int nb = 0; nb < 8; nb++) {
            *(float2*)(wbase + qr * 64 + nb * 8 + qc)       = make_float2(oacc[nb][0], oacc[nb][1]);
            *(float2*)(wbase + (qr + 8) * 64 + nb * 8 + qc) = make_float2(oacc[nb][2], oacc[nb][3]);
        }
    }
    __syncthreads();

    // final: out[rl][n] = stg[warp 2s] + stg[warp 2s+1] + bias, rl = s*16+rr
    {
        float* orow = out + ((size_t)b * 64) * 64;
        #pragma unroll
        for (int q = 0; q < 4; q++) {
            int e  = tid * 16 + q * 4;        // 0..4095 over 64x64 block
            int rl = e >> 6;
            int n  = e & 63;
            int s  = rl >> 4;
            int rr = rl & 15;
            float4 a = *(float4*)(stg + (2 * s) * 1024 + rr * 64 + n);
            float4 c = *(float4*)(stg + (2 * s + 1) * 1024 + rr * 64 + n);
            float4 bv = *(const float4*)(bias + n);
            *(float4*)(orow + rl * 64 + n) =
                make_float4(a.x + c.x + bv.x, a.y + c.y + bv.y,
                            a.z + c.z + bv.z, a.w + c.w + bv.w);
        }
    }
}

extern "C" void kernel_launch(void* const* d_in, const int* in_sizes, int n_in,
                              void* d_out, int out_size)
{
    const float* hidden = (const float*)d_in[0];
    const float* pos    = (const float*)d_in[1];
    const float* weight = (const float*)d_in[2];
    const float* bias   = (const float*)d_in[3];
    float* out = (float*)d_out;

    const int total = in_sizes[0] / 128;     // 16384 rows
    const int nscene = total / 64;           // 256

    sp_wprep<<<128, 256>>>(weight);

    cudaFuncSetAttribute(sp_main, cudaFuncAttributeMaxDynamicSharedMemorySize, SMEM_MAIN);
    sp_main<<<nscene, TPB, SMEM_MAIN>>>(hidden, pos, bias, out);
}